// round 1
// baseline (speedup 1.0000x reference)
#include <cuda_runtime.h>
#include <math.h>

#define Bb 64
#define LTt 512
#define LFf 512
#define DD 512

// ---------------- scratch (device globals; no allocation allowed) -----------
__device__ float g_proj[(size_t)Bb * LTt * DD];   // 64 MB
__device__ float g_mt[Bb * LTt];
__device__ float g_mf[Bb * LFf];
__device__ float g_rowmax[Bb * LTt];
__device__ float g_colmax[Bb * LFf];
__device__ float g_alpha_t[Bb * LTt];
__device__ float g_alpha_f[Bb * LFf];
__device__ int   g_mask_fmt;                      // 0=int32, 1=float32, 2=uint8

// ---------------- helpers ----------------------------------------------------
__device__ __forceinline__ void atomicMaxF(float* a, float v) {
    if (v >= 0.0f) atomicMax((int*)a, __float_as_int(v));
    else           atomicMin((unsigned int*)a, __float_as_uint(v));
}

__device__ __forceinline__ float load_mask(const void* p, int i, int fmt) {
    if (fmt == 0) return ((const int*)p)[i] ? 1.0f : 0.0f;
    if (fmt == 1) return ((const float*)p)[i];
    return ((const unsigned char*)p)[i] ? 1.0f : 0.0f;
}

// ---------------- kernel 0: detect mask dtype --------------------------------
__global__ void detect_kernel(const unsigned int* m) {
    if (threadIdx.x == 0 && blockIdx.x == 0) {
        bool i32 = true, f32 = true;
        for (int i = 0; i < 256; i++) {
            unsigned int w = m[i];
            if (w > 1u) i32 = false;
            if (w != 0u && w != 0x3F800000u) f32 = false;
        }
        g_mask_fmt = i32 ? 0 : (f32 ? 1 : 2);
    }
}

// ---------------- kernel 1: expand masks to f32 + init maxes -----------------
__global__ void prep_kernel(const void* mt, const void* mf) {
    int i = blockIdx.x * blockDim.x + threadIdx.x;
    if (i >= Bb * LTt) return;
    int fmt = g_mask_fmt;
    g_mt[i] = load_mask(mt, i, fmt);
    g_mf[i] = load_mask(mf, i, fmt);
    float ninf = __int_as_float(0xff800000);
    g_rowmax[i] = ninf;
    g_colmax[i] = ninf;
}

// ---------------- kernel 2: proj = (t * m_t) @ W  (NN sgemm) -----------------
__global__ void __launch_bounds__(256) gemm_proj_kernel(
    const float* __restrict__ T, const float* __restrict__ W)
{
    const int b  = blockIdx.z;
    const int l0 = blockIdx.y * 128;
    const int n0 = blockIdx.x * 128;
    const float* A  = T + (size_t)b * LTt * DD;
    const float* MR = g_mt + b * LTt;
    float* C = g_proj + (size_t)b * LTt * DD;

    __shared__ float As[16][132];   // k-major, padded for LDS.128 + low conflicts
    __shared__ float Bs[16][128];

    const int tid = threadIdx.x;
    const int tx = tid & 15;
    const int ty = tid >> 4;

    float acc[8][8];
    #pragma unroll
    for (int i = 0; i < 8; i++)
        #pragma unroll
        for (int j = 0; j < 8; j++) acc[i][j] = 0.0f;

    for (int k0 = 0; k0 < DD; k0 += 16) {
        // A tile [128 x 16], transpose into As, apply row mask
        #pragma unroll
        for (int j = 0; j < 2; j++) {
            int f4 = tid + 256 * j;
            int r  = f4 >> 2;
            int c4 = f4 & 3;
            float4 v = *(const float4*)(A + (size_t)(l0 + r) * DD + k0 + c4 * 4);
            float mm = MR[l0 + r];
            As[c4 * 4 + 0][r] = v.x * mm;
            As[c4 * 4 + 1][r] = v.y * mm;
            As[c4 * 4 + 2][r] = v.z * mm;
            As[c4 * 4 + 3][r] = v.w * mm;
        }
        // W tile [16 x 128], direct
        #pragma unroll
        for (int j = 0; j < 2; j++) {
            int f4 = tid + 256 * j;
            int kr = f4 >> 5;
            int c4 = f4 & 31;
            *(float4*)&Bs[kr][c4 * 4] =
                *(const float4*)(W + (size_t)(k0 + kr) * DD + n0 + c4 * 4);
        }
        __syncthreads();
        #pragma unroll
        for (int k = 0; k < 16; k++) {
            float4 a0 = *(const float4*)&As[k][ty * 8];
            float4 a1 = *(const float4*)&As[k][ty * 8 + 4];
            float4 b0 = *(const float4*)&Bs[k][tx * 8];
            float4 b1 = *(const float4*)&Bs[k][tx * 8 + 4];
            float av[8] = {a0.x, a0.y, a0.z, a0.w, a1.x, a1.y, a1.z, a1.w};
            float bv[8] = {b0.x, b0.y, b0.z, b0.w, b1.x, b1.y, b1.z, b1.w};
            #pragma unroll
            for (int i = 0; i < 8; i++)
                #pragma unroll
                for (int j = 0; j < 8; j++)
                    acc[i][j] = fmaf(av[i], bv[j], acc[i][j]);
        }
        __syncthreads();
    }

    #pragma unroll
    for (int i = 0; i < 8; i++) {
        float4 o0 = make_float4(acc[i][0], acc[i][1], acc[i][2], acc[i][3]);
        float4 o1 = make_float4(acc[i][4], acc[i][5], acc[i][6], acc[i][7]);
        float* cp = C + (size_t)(l0 + ty * 8 + i) * DD + n0 + tx * 8;
        *(float4*)cp       = o0;
        *(float4*)(cp + 4) = o1;
    }
}

// ------- kernel 3: M = proj @ (f*m_f)^T (NT) with fused row/col max ----------
__global__ void __launch_bounds__(256) gemm_score_kernel(const float* __restrict__ F)
{
    const int b  = blockIdx.z;
    const int l0 = blockIdx.y * 128;   // LT rows
    const int m0 = blockIdx.x * 128;   // LF cols
    const float* A  = g_proj + (size_t)b * LTt * DD;
    const float* Bm = F + (size_t)b * LFf * DD;
    const float* MC = g_mf + b * LFf;

    __shared__ float As[16][132];
    __shared__ float Bs[16][132];
    __shared__ float s_rmax[128];
    __shared__ float s_cmax[128];

    const int tid = threadIdx.x;
    const int tx = tid & 15;
    const int ty = tid >> 4;
    const float ninf = __int_as_float(0xff800000);

    if (tid < 128) { s_rmax[tid] = ninf; s_cmax[tid] = ninf; }

    float acc[8][8];
    #pragma unroll
    for (int i = 0; i < 8; i++)
        #pragma unroll
        for (int j = 0; j < 8; j++) acc[i][j] = 0.0f;

    for (int k0 = 0; k0 < DD; k0 += 16) {
        // proj tile [128 x 16] -> As (no mask; already masked)
        #pragma unroll
        for (int j = 0; j < 2; j++) {
            int f4 = tid + 256 * j;
            int r  = f4 >> 2;
            int c4 = f4 & 3;
            float4 v = *(const float4*)(A + (size_t)(l0 + r) * DD + k0 + c4 * 4);
            As[c4 * 4 + 0][r] = v.x;
            As[c4 * 4 + 1][r] = v.y;
            As[c4 * 4 + 2][r] = v.z;
            As[c4 * 4 + 3][r] = v.w;
        }
        // f tile [128 m-rows x 16 d] -> Bs (transpose + column mask)
        #pragma unroll
        for (int j = 0; j < 2; j++) {
            int f4 = tid + 256 * j;
            int r  = f4 >> 2;
            int c4 = f4 & 3;
            float4 v = *(const float4*)(Bm + (size_t)(m0 + r) * DD + k0 + c4 * 4);
            float mm = MC[m0 + r];
            Bs[c4 * 4 + 0][r] = v.x * mm;
            Bs[c4 * 4 + 1][r] = v.y * mm;
            Bs[c4 * 4 + 2][r] = v.z * mm;
            Bs[c4 * 4 + 3][r] = v.w * mm;
        }
        __syncthreads();
        #pragma unroll
        for (int k = 0; k < 16; k++) {
            float4 a0 = *(const float4*)&As[k][ty * 8];
            float4 a1 = *(const float4*)&As[k][ty * 8 + 4];
            float4 b0 = *(const float4*)&Bs[k][tx * 8];
            float4 b1 = *(const float4*)&Bs[k][tx * 8 + 4];
            float av[8] = {a0.x, a0.y, a0.z, a0.w, a1.x, a1.y, a1.z, a1.w};
            float bv[8] = {b0.x, b0.y, b0.z, b0.w, b1.x, b1.y, b1.z, b1.w};
            #pragma unroll
            for (int i = 0; i < 8; i++)
                #pragma unroll
                for (int j = 0; j < 8; j++)
                    acc[i][j] = fmaf(av[i], bv[j], acc[i][j]);
        }
        __syncthreads();
    }

    // per-thread tile row/col maxes -> shared -> global (tanh deferred: monotone)
    #pragma unroll
    for (int i = 0; i < 8; i++) {
        float rm = acc[i][0];
        #pragma unroll
        for (int j = 1; j < 8; j++) rm = fmaxf(rm, acc[i][j]);
        atomicMaxF(&s_rmax[ty * 8 + i], rm);
    }
    #pragma unroll
    for (int j = 0; j < 8; j++) {
        float cm = acc[0][j];
        #pragma unroll
        for (int i = 1; i < 8; i++) cm = fmaxf(cm, acc[i][j]);
        atomicMaxF(&s_cmax[tx * 8 + j], cm);
    }
    __syncthreads();
    if (tid < 128) atomicMaxF(&g_rowmax[b * LTt + l0 + tid], s_rmax[tid]);
    else           atomicMaxF(&g_colmax[b * LFf + m0 + (tid - 128)], s_cmax[tid - 128]);
}

// ---------------- kernel 4: masked softmax -> alpha (mask folded in) ---------
__global__ void softmax_kernel() {
    const int idx = blockIdx.x;          // [0, 2B)
    const bool isF = idx >= Bb;
    const int b = isF ? idx - Bb : idx;
    const float* mx = isF ? (g_colmax + b * LFf) : (g_rowmax + b * LTt);
    const float* mk = isF ? (g_mf + b * LFf)     : (g_mt + b * LTt);
    float* out      = isF ? (g_alpha_f + b * LFf) : (g_alpha_t + b * LTt);

    const int tid = threadIdx.x;         // 256 threads, 2 elems each (L = 512)
    int i0 = tid, i1 = tid + 256;
    float m0v = mk[i0], m1v = mk[i1];
    float v0 = tanhf(mx[i0]) + (m0v - 1.0f) * 1000000.0f;
    float v1 = tanhf(mx[i1]) + (m1v - 1.0f) * 1000000.0f;

    __shared__ float red[256];
    red[tid] = fmaxf(v0, v1);
    __syncthreads();
    for (int s = 128; s > 0; s >>= 1) {
        if (tid < s) red[tid] = fmaxf(red[tid], red[tid + s]);
        __syncthreads();
    }
    float vm = red[0];
    __syncthreads();

    float e0 = expf(v0 - vm);
    float e1 = expf(v1 - vm);
    red[tid] = e0 + e1;
    __syncthreads();
    for (int s = 128; s > 0; s >>= 1) {
        if (tid < s) red[tid] += red[tid + s];
        __syncthreads();
    }
    float inv = 1.0f / red[0];
    // fold mask into alpha: sum_l (t*m)*alpha == sum_l t*(alpha*m) exactly
    out[i0] = e0 * inv * m0v;
    out[i1] = e1 * inv * m1v;
}

// ---------------- kernel 5: out = alpha_t^T t + alpha_f^T f ------------------
__global__ void combine_kernel(const float* __restrict__ T,
                               const float* __restrict__ F,
                               float* __restrict__ out)
{
    const int b = blockIdx.y;
    const int d = blockIdx.x * 128 + threadIdx.x;
    const float* at = g_alpha_t + b * LTt;
    const float* af = g_alpha_f + b * LFf;
    const float* tp = T + (size_t)b * LTt * DD + d;
    const float* fp = F + (size_t)b * LFf * DD + d;

    float a0 = 0.f, a1 = 0.f, a2 = 0.f, a3 = 0.f;
    #pragma unroll 4
    for (int l = 0; l < LTt; l += 4) {
        a0 = fmaf(at[l + 0], tp[(size_t)(l + 0) * DD], a0);
        a1 = fmaf(at[l + 1], tp[(size_t)(l + 1) * DD], a1);
        a2 = fmaf(at[l + 2], tp[(size_t)(l + 2) * DD], a2);
        a3 = fmaf(at[l + 3], tp[(size_t)(l + 3) * DD], a3);
    }
    #pragma unroll 4
    for (int m = 0; m < LFf; m += 4) {
        a0 = fmaf(af[m + 0], fp[(size_t)(m + 0) * DD], a0);
        a1 = fmaf(af[m + 1], fp[(size_t)(m + 1) * DD], a1);
        a2 = fmaf(af[m + 2], fp[(size_t)(m + 2) * DD], a2);
        a3 = fmaf(af[m + 3], fp[(size_t)(m + 3) * DD], a3);
    }
    out[b * DD + d] = (a0 + a1) + (a2 + a3);
}

// ---------------- launch ------------------------------------------------------
extern "C" void kernel_launch(void* const* d_in, const int* in_sizes, int n_in,
                              void* d_out, int out_size)
{
    const float* t  = (const float*)d_in[0];
    const float* f  = (const float*)d_in[1];
    const void*  mt = d_in[2];
    const void*  mf = d_in[3];
    const float* w  = (const float*)d_in[4];
    float* out = (float*)d_out;

    detect_kernel<<<1, 32>>>((const unsigned int*)mt);
    prep_kernel<<<(Bb * LTt + 255) / 256, 256>>>(mt, mf);
    gemm_proj_kernel<<<dim3(4, 4, Bb), 256>>>(t, w);
    gemm_score_kernel<<<dim3(4, 4, Bb), 256>>>(f);
    softmax_kernel<<<2 * Bb, 256>>>();
    combine_kernel<<<dim3(4, Bb), 128>>>(t, f, out);
}

// round 3
// speedup vs baseline: 2.1816x; 2.1816x over previous
#include <cuda_runtime.h>
#include <math.h>
#include <stdint.h>

#define Bb 64
#define LL 512
#define DD 512

// ----------------------------- scratch ---------------------------------------
__device__ float g_proj[(size_t)Bb * LL * DD];   // 64 MB
__device__ float g_wt[DD * DD];                  // W^T
__device__ float g_mt[Bb * LL];
__device__ float g_mf[Bb * LL];
__device__ float g_rowmax[Bb * LL];
__device__ float g_colmax[Bb * LL];
__device__ float g_alpha_t[Bb * LL];
__device__ float g_alpha_f[Bb * LL];
__device__ int   g_mask_fmt;

// ----------------------------- helpers ---------------------------------------
__device__ __forceinline__ uint32_t tf32r(float x) {
    float y;
    asm("cvt.rna.tf32.f32 %0, %1;" : "=f"(y) : "f"(x));
    return __float_as_uint(y);
}

__device__ __forceinline__ void mma_tf32(float* c, const uint32_t* a, const uint32_t* b) {
    asm volatile(
        "mma.sync.aligned.m16n8k8.row.col.f32.tf32.tf32.f32 "
        "{%0,%1,%2,%3}, {%4,%5,%6,%7}, {%8,%9}, {%0,%1,%2,%3};\n"
        : "+f"(c[0]), "+f"(c[1]), "+f"(c[2]), "+f"(c[3])
        : "r"(a[0]), "r"(a[1]), "r"(a[2]), "r"(a[3]), "r"(b[0]), "r"(b[1]));
}

__device__ __forceinline__ void atomicMaxF(float* a, float v) {
    if (v >= 0.0f) atomicMax((int*)a, __float_as_int(v));
    else           atomicMin((unsigned int*)a, __float_as_uint(v));
}

__device__ __forceinline__ float load_mask(const void* p, int i, int fmt) {
    if (fmt == 0) return ((const int*)p)[i] ? 1.0f : 0.0f;
    if (fmt == 1) return ((const float*)p)[i];
    return ((const unsigned char*)p)[i] ? 1.0f : 0.0f;
}

// ----------------------------- small kernels ----------------------------------
__global__ void detect_kernel(const unsigned int* m) {
    if (threadIdx.x == 0 && blockIdx.x == 0) {
        bool i32 = true, f32 = true;
        for (int i = 0; i < 256; i++) {
            unsigned int w = m[i];
            if (w > 1u) i32 = false;
            if (w != 0u && w != 0x3F800000u) f32 = false;
        }
        g_mask_fmt = i32 ? 0 : (f32 ? 1 : 2);
    }
}

__global__ void prep_kernel(const void* mt, const void* mf) {
    int i = blockIdx.x * blockDim.x + threadIdx.x;
    if (i >= Bb * LL) return;
    int fmt = g_mask_fmt;
    g_mt[i] = load_mask(mt, i, fmt);
    g_mf[i] = load_mask(mf, i, fmt);
    float ninf = __int_as_float(0xff800000);
    g_rowmax[i] = ninf;
    g_colmax[i] = ninf;
}

__global__ void transpose_w(const float* __restrict__ W) {
    __shared__ float tile[32][33];
    int tx = threadIdx.x, ty = threadIdx.y;
    int x = blockIdx.x * 32 + tx;
    int y0 = blockIdx.y * 32;
#pragma unroll
    for (int j = 0; j < 32; j += 8)
        tile[ty + j][tx] = W[(size_t)(y0 + ty + j) * DD + x];
    __syncthreads();
    int xo = y0 + tx;
    int yo0 = blockIdx.x * 32;
#pragma unroll
    for (int j = 0; j < 32; j += 8)
        g_wt[(size_t)(yo0 + ty + j) * DD + xo] = tile[tx][ty + j];
}

// ----------------------------- tf32 mma GEMM -----------------------------------
// Both modes compute D[l,n] = sum_k A[l,k] * B[n,k]   (NT form)
// MODE 0: A = t (masked rows, m_t), B = g_wt          -> D = proj  (write g_proj)
// MODE 1: A = g_proj,            B = f (masked, m_f)  -> row/col max only
#define BK 16
#define SROW 20   // padded row stride in floats (16B aligned, conflict-free)

template <int MODE>
__global__ void __launch_bounds__(256, 2) mma_gemm(const float* __restrict__ Ag,
                                                   const float* __restrict__ Bg)
{
    __shared__ uint32_t As[2][128][SROW];
    __shared__ uint32_t Bs[2][128][SROW];
    __shared__ float s_rmax[128];
    __shared__ float s_cmax[128];

    const int tid  = threadIdx.x;
    const int lane = tid & 31;
    const int wid  = tid >> 5;
    const int wm   = wid & 1;     // 2 warps in M
    const int wn   = wid >> 1;    // 4 warps in N
    const int b  = blockIdx.z;
    const int l0 = blockIdx.y * 128;
    const int n0 = blockIdx.x * 128;

    const float* Aptr;
    const float* Bptr;
    float ma0 = 1.f, ma1 = 1.f, mb0 = 1.f, mb1 = 1.f;

    const int gr = tid >> 2;        // 0..63
    const int gc = (tid & 3) * 4;   // 0,4,8,12

    if (MODE == 0) {
        Aptr = Ag + (size_t)b * LL * DD;
        Bptr = g_wt;
        ma0 = g_mt[b * LL + l0 + gr];
        ma1 = g_mt[b * LL + l0 + gr + 64];
    } else {
        Aptr = g_proj + (size_t)b * LL * DD;
        Bptr = Bg + (size_t)b * LL * DD;
        mb0 = g_mf[b * LL + n0 + gr];
        mb1 = g_mf[b * LL + n0 + gr + 64];
    }

    if (MODE == 1 && tid < 128) {
        s_rmax[tid] = __int_as_float(0xff800000);
        s_cmax[tid] = __int_as_float(0xff800000);
    }

    const float* Ab0 = Aptr + (size_t)(l0 + gr) * DD + gc;
    const float* Ab1 = Aptr + (size_t)(l0 + gr + 64) * DD + gc;
    const float* Bb0 = Bptr + (size_t)(n0 + gr) * DD + gc;
    const float* Bb1 = Bptr + (size_t)(n0 + gr + 64) * DD + gc;

    float acc[4][4][4];
#pragma unroll
    for (int i = 0; i < 4; i++)
#pragma unroll
        for (int j = 0; j < 4; j++)
#pragma unroll
            for (int q = 0; q < 4; q++) acc[i][j][q] = 0.0f;

    // ---- prologue: load k-chunk 0 into buf 0
    {
        float4 va0 = *(const float4*)Ab0;
        float4 va1 = *(const float4*)Ab1;
        float4 vb0 = *(const float4*)Bb0;
        float4 vb1 = *(const float4*)Bb1;
        As[0][gr     ][gc + 0] = tf32r(va0.x * ma0);
        As[0][gr     ][gc + 1] = tf32r(va0.y * ma0);
        As[0][gr     ][gc + 2] = tf32r(va0.z * ma0);
        As[0][gr     ][gc + 3] = tf32r(va0.w * ma0);
        As[0][gr + 64][gc + 0] = tf32r(va1.x * ma1);
        As[0][gr + 64][gc + 1] = tf32r(va1.y * ma1);
        As[0][gr + 64][gc + 2] = tf32r(va1.z * ma1);
        As[0][gr + 64][gc + 3] = tf32r(va1.w * ma1);
        Bs[0][gr     ][gc + 0] = tf32r(vb0.x * mb0);
        Bs[0][gr     ][gc + 1] = tf32r(vb0.y * mb0);
        Bs[0][gr     ][gc + 2] = tf32r(vb0.z * mb0);
        Bs[0][gr     ][gc + 3] = tf32r(vb0.w * mb0);
        Bs[0][gr + 64][gc + 0] = tf32r(vb1.x * mb1);
        Bs[0][gr + 64][gc + 1] = tf32r(vb1.y * mb1);
        Bs[0][gr + 64][gc + 2] = tf32r(vb1.z * mb1);
        Bs[0][gr + 64][gc + 3] = tf32r(vb1.w * mb1);
    }
    __syncthreads();

    const int NKT = DD / BK;   // 32
    for (int kt = 0; kt < NKT; kt++) {
        const int buf = kt & 1;
        float4 va0, va1, vb0, vb1;
        if (kt + 1 < NKT) {
            const int K0 = (kt + 1) * BK;
            va0 = *(const float4*)(Ab0 + K0);
            va1 = *(const float4*)(Ab1 + K0);
            vb0 = *(const float4*)(Bb0 + K0);
            vb1 = *(const float4*)(Bb1 + K0);
        }

#pragma unroll
        for (int kk = 0; kk < 2; kk++) {
            const int k = kk * 8 + (lane & 3);
            uint32_t af[4][4];
#pragma unroll
            for (int mt = 0; mt < 4; mt++) {
                const int row = wm * 64 + mt * 16 + (lane >> 2);
                af[mt][0] = As[buf][row    ][k];
                af[mt][1] = As[buf][row + 8][k];
                af[mt][2] = As[buf][row    ][k + 4];
                af[mt][3] = As[buf][row + 8][k + 4];
            }
            uint32_t bf[4][2];
#pragma unroll
            for (int nt = 0; nt < 4; nt++) {
                const int n = wn * 32 + nt * 8 + (lane >> 2);
                bf[nt][0] = Bs[buf][n][k];
                bf[nt][1] = Bs[buf][n][k + 4];
            }
#pragma unroll
            for (int mt = 0; mt < 4; mt++)
#pragma unroll
                for (int nt = 0; nt < 4; nt++)
                    mma_tf32(acc[mt][nt], af[mt], bf[nt]);
        }

        if (kt + 1 < NKT) {
            const int nb = (kt + 1) & 1;
            As[nb][gr     ][gc + 0] = tf32r(va0.x * ma0);
            As[nb][gr     ][gc + 1] = tf32r(va0.y * ma0);
            As[nb][gr     ][gc + 2] = tf32r(va0.z * ma0);
            As[nb][gr     ][gc + 3] = tf32r(va0.w * ma0);
            As[nb][gr + 64][gc + 0] = tf32r(va1.x * ma1);
            As[nb][gr + 64][gc + 1] = tf32r(va1.y * ma1);
            As[nb][gr + 64][gc + 2] = tf32r(va1.z * ma1);
            As[nb][gr + 64][gc + 3] = tf32r(va1.w * ma1);
            Bs[nb][gr     ][gc + 0] = tf32r(vb0.x * mb0);
            Bs[nb][gr     ][gc + 1] = tf32r(vb0.y * mb0);
            Bs[nb][gr     ][gc + 2] = tf32r(vb0.z * mb0);
            Bs[nb][gr     ][gc + 3] = tf32r(vb0.w * mb0);
            Bs[nb][gr + 64][gc + 0] = tf32r(vb1.x * mb1);
            Bs[nb][gr + 64][gc + 1] = tf32r(vb1.y * mb1);
            Bs[nb][gr + 64][gc + 2] = tf32r(vb1.z * mb1);
            Bs[nb][gr + 64][gc + 3] = tf32r(vb1.w * mb1);
            __syncthreads();
        }
    }

    // ----------------------------- epilogue -------------------------------------
    if (MODE == 0) {
        float* Crow = g_proj + (size_t)b * LL * DD;
#pragma unroll
        for (int mt = 0; mt < 4; mt++) {
            const int r = l0 + wm * 64 + mt * 16 + (lane >> 2);
#pragma unroll
            for (int nt = 0; nt < 4; nt++) {
                const int c = n0 + wn * 32 + nt * 8 + 2 * (lane & 3);
                float2 o0 = make_float2(acc[mt][nt][0], acc[mt][nt][1]);
                float2 o1 = make_float2(acc[mt][nt][2], acc[mt][nt][3]);
                *(float2*)(Crow + (size_t)r * DD + c)       = o0;
                *(float2*)(Crow + (size_t)(r + 8) * DD + c) = o1;
            }
        }
    } else {
        __syncthreads();
        const float NINF = __int_as_float(0xff800000);
        // row maxes: rows owned by this thread
#pragma unroll
        for (int mt = 0; mt < 4; mt++) {
#pragma unroll
            for (int h = 0; h < 2; h++) {
                float v = NINF;
#pragma unroll
                for (int nt = 0; nt < 4; nt++)
                    v = fmaxf(v, fmaxf(acc[mt][nt][2 * h], acc[mt][nt][2 * h + 1]));
                v = fmaxf(v, __shfl_xor_sync(0xffffffffu, v, 1));
                v = fmaxf(v, __shfl_xor_sync(0xffffffffu, v, 2));
                if ((lane & 3) == 0) {
                    int row = wm * 64 + mt * 16 + (lane >> 2) + h * 8;
                    atomicMaxF(&s_rmax[row], v);
                }
            }
        }
        // col maxes
#pragma unroll
        for (int nt = 0; nt < 4; nt++) {
#pragma unroll
            for (int j = 0; j < 2; j++) {
                float v = NINF;
#pragma unroll
                for (int mt = 0; mt < 4; mt++)
                    v = fmaxf(v, fmaxf(acc[mt][nt][j], acc[mt][nt][2 + j]));
                v = fmaxf(v, __shfl_xor_sync(0xffffffffu, v, 4));
                v = fmaxf(v, __shfl_xor_sync(0xffffffffu, v, 8));
                v = fmaxf(v, __shfl_xor_sync(0xffffffffu, v, 16));
                if (lane < 4) {
                    int col = wn * 32 + nt * 8 + 2 * lane + j;
                    atomicMaxF(&s_cmax[col], v);
                }
            }
        }
        __syncthreads();
        if (tid < 128) {
            atomicMaxF(&g_rowmax[b * LL + l0 + tid], s_rmax[tid]);
            atomicMaxF(&g_colmax[b * LL + n0 + tid], s_cmax[tid]);
        }
    }
}

// ----------------------------- softmax ----------------------------------------
__global__ void softmax_kernel() {
    const int idx = blockIdx.x;
    const bool isF = idx >= Bb;
    const int b = isF ? idx - Bb : idx;
    const float* mx = isF ? (g_colmax + b * LL) : (g_rowmax + b * LL);
    const float* mk = isF ? (g_mf + b * LL) : (g_mt + b * LL);
    float* out = isF ? (g_alpha_f + b * LL) : (g_alpha_t + b * LL);

    const int tid = threadIdx.x;
    int i0 = tid, i1 = tid + 256;
    float m0v = mk[i0], m1v = mk[i1];
    float v0 = tanhf(mx[i0]) + (m0v - 1.0f) * 1000000.0f;
    float v1 = tanhf(mx[i1]) + (m1v - 1.0f) * 1000000.0f;

    __shared__ float red[256];
    red[tid] = fmaxf(v0, v1);
    __syncthreads();
    for (int s = 128; s > 0; s >>= 1) {
        if (tid < s) red[tid] = fmaxf(red[tid], red[tid + s]);
        __syncthreads();
    }
    float vm = red[0];
    __syncthreads();

    float e0 = expf(v0 - vm);
    float e1 = expf(v1 - vm);
    red[tid] = e0 + e1;
    __syncthreads();
    for (int s = 128; s > 0; s >>= 1) {
        if (tid < s) red[tid] += red[tid + s];
        __syncthreads();
    }
    float inv = 1.0f / red[0];
    out[i0] = e0 * inv * m0v;
    out[i1] = e1 * inv * m1v;
}

// ----------------------------- combine -----------------------------------------
__global__ void combine_kernel(const float* __restrict__ T,
                               const float* __restrict__ F,
                               float* __restrict__ out)
{
    const int b = blockIdx.y;
    const int d = blockIdx.x * 128 + threadIdx.x;
    const float* at = g_alpha_t + b * LL;
    const float* af = g_alpha_f + b * LL;
    const float* tp = T + (size_t)b * LL * DD + d;
    const float* fp = F + (size_t)b * LL * DD + d;

    float a0 = 0.f, a1 = 0.f, a2 = 0.f, a3 = 0.f;
#pragma unroll 4
    for (int l = 0; l < LL; l += 4) {
        a0 = fmaf(at[l + 0], tp[(size_t)(l + 0) * DD], a0);
        a1 = fmaf(at[l + 1], tp[(size_t)(l + 1) * DD], a1);
        a2 = fmaf(at[l + 2], tp[(size_t)(l + 2) * DD], a2);
        a3 = fmaf(at[l + 3], tp[(size_t)(l + 3) * DD], a3);
    }
#pragma unroll 4
    for (int m = 0; m < LL; m += 4) {
        a0 = fmaf(af[m + 0], fp[(size_t)(m + 0) * DD], a0);
        a1 = fmaf(af[m + 1], fp[(size_t)(m + 1) * DD], a1);
        a2 = fmaf(af[m + 2], fp[(size_t)(m + 2) * DD], a2);
        a3 = fmaf(af[m + 3], fp[(size_t)(m + 3) * DD], a3);
    }
    out[b * DD + d] = (a0 + a1) + (a2 + a3);
}

// ----------------------------- launch -------------------------------------------
extern "C" void kernel_launch(void* const* d_in, const int* in_sizes, int n_in,
                              void* d_out, int out_size)
{
    const float* t  = (const float*)d_in[0];
    const float* f  = (const float*)d_in[1];
    const void*  mt = d_in[2];
    const void*  mf = d_in[3];
    const float* w  = (const float*)d_in[4];
    float* out = (float*)d_out;

    detect_kernel<<<1, 32>>>((const unsigned int*)mt);
    prep_kernel<<<(Bb * LL + 255) / 256, 256>>>(mt, mf);
    transpose_w<<<dim3(16, 16), dim3(32, 8)>>>(w);
    mma_gemm<0><<<dim3(4, 4, Bb), 256>>>(t, nullptr);
    mma_gemm<1><<<dim3(4, 4, Bb), 256>>>(nullptr, f);
    softmax_kernel<<<2 * Bb, 256>>>();
    combine_kernel<<<dim3(4, Bb), 128>>>(t, f, out);
}